// round 5
// baseline (speedup 1.0000x reference)
#include <cuda_runtime.h>
#include <cuda_bf16.h>
#include <stdint.h>
#include <math.h>

#define N_NODES 10000
#define N_EDGES 100000
#define F_NODE 128
#define F_EDGE 16
#define HEADS 8
#define OUT_CH 128
#define HC 1024
#define NQKVS 3200   // 3*1024 + 128 fused output columns

// ---------------- scratch (device globals) ----------------
__device__ __nv_bfloat16 d_xh[N_NODES * 128];
__device__ __nv_bfloat16 d_xl[N_NODES * 128];
__device__ __nv_bfloat16 d_qb[N_NODES * HC];
__device__ __nv_bfloat16 d_kb[N_NODES * HC];
__device__ __nv_bfloat16 d_vb[N_NODES * HC];
__device__ __nv_bfloat16 d_Bb[N_NODES * 128];
__device__ __nv_bfloat16 d_Wqh[128 * NQKVS];
__device__ __nv_bfloat16 d_Wql[128 * NQKVS];
__device__ __nv_bfloat16 d_Wgh[1024 * 128];
__device__ __nv_bfloat16 d_Wgl[1024 * 128];
__device__ __nv_bfloat16 d_Werh[128 * 128];
__device__ __nv_bfloat16 d_Werl[128 * 128];
__device__ float d_biasc[NQKVS];
__device__ float d_skip[N_NODES * 128];
__device__ float d_g[N_NODES * 128];
__device__ float d_aexp[N_EDGES * HEADS];  // indexed by SORTED position
__device__ float d_s[N_NODES * HEADS];
__device__ float d_vout[N_NODES * 128];
__device__ float d_pooled[128];
// sort scratch
__device__ int d_cnt[N_NODES];
__device__ int d_off[N_NODES + 1];
__device__ int d_pos[N_NODES];
__device__ int d_ssrc[N_EDGES];
__device__ int d_seid[N_EDGES];

// ---------------- fused prep: split_x | pack_w | bias | build_wg | build_wer ----
#define SEG0 (N_NODES * 128)
#define SEG1 (128 * NQKVS)
#define SEG2 (NQKVS)
#define SEG3 (1024 * 128)
#define SEG4 (128 * 128)
#define PREP_TOTAL (SEG0 + SEG1 + SEG2 + SEG3 + SEG4)

__global__ __launch_bounds__(256) void prep_all(
    const float* __restrict__ x, const float* __restrict__ Wq,
    const float* __restrict__ Wk, const float* __restrict__ Wv,
    const float* __restrict__ Ws, const float* __restrict__ bq,
    const float* __restrict__ bk, const float* __restrict__ bv,
    const float* __restrict__ bs, const float* __restrict__ We) {
    int idx = blockIdx.x * 256 + threadIdx.x;
    if (idx < SEG0) {
        float v = x[idx];
        __nv_bfloat16 h = __float2bfloat16(v);
        d_xh[idx] = h;
        d_xl[idx] = __float2bfloat16(v - __bfloat162float(h));
        return;
    }
    idx -= SEG0;
    if (idx < SEG1) {
        int k = idx / NQKVS, col = idx % NQKVS;
        float v;
        if (col < 1024) v = Wq[k * HC + col];
        else if (col < 2048) v = Wk[k * HC + col - 1024];
        else if (col < 3072) v = Wv[k * HC + col - 2048];
        else v = Ws[k * 128 + col - 3072];
        __nv_bfloat16 h = __float2bfloat16(v);
        d_Wqh[idx] = h;
        d_Wql[idx] = __float2bfloat16(v - __bfloat162float(h));
        return;
    }
    idx -= SEG1;
    if (idx < SEG2) {
        float b;
        if (idx < 1024) b = bq[idx];
        else if (idx < 2048) b = bk[idx - 1024];
        else if (idx < 3072) b = bv[idx - 2048];
        else b = bs[idx - 3072];
        d_biasc[idx] = b;
        return;
    }
    idx -= SEG2;
    if (idx < SEG3) {
        int k = idx >> 7, j = idx & 127;
        int h = j >> 4, f = j & 15;
        int c = k & 127, hk = k >> 7;
        float v = (hk == h) ? We[f * HC + h * 128 + c] : 0.f;
        __nv_bfloat16 hh = __float2bfloat16(v);
        d_Wgh[idx] = hh;
        d_Wgl[idx] = __float2bfloat16(v - __bfloat162float(hh));
        return;
    }
    idx -= SEG3;
    if (idx < SEG4) {
        int j = idx >> 7, c = idx & 127;
        int h = j >> 4, f = j & 15;
        float v = We[f * HC + h * 128 + c];
        __nv_bfloat16 hh = __float2bfloat16(v);
        d_Werh[idx] = hh;
        d_Werl[idx] = __float2bfloat16(v - __bfloat162float(hh));
    }
}

// ---------------- counting sort by dst ----------------
__global__ __launch_bounds__(256) void hist_kernel(const int* __restrict__ eidx) {
    int e = blockIdx.x * 256 + threadIdx.x;
    if (e < N_EDGES) atomicAdd(&d_cnt[eidx[N_EDGES + e]], 1);
}

__global__ __launch_bounds__(1024) void scan_kernel() {
    __shared__ int sdata[1024];
    __shared__ int srun;
    int tid = threadIdx.x;
    if (tid == 0) srun = 0;
    __syncthreads();
    for (int base = 0; base < N_NODES; base += 1024) {
        int i = base + tid;
        int v = (i < N_NODES) ? d_cnt[i] : 0;
        sdata[tid] = v;
        __syncthreads();
        for (int off = 1; off < 1024; off <<= 1) {
            int t = (tid >= off) ? sdata[tid - off] : 0;
            __syncthreads();
            sdata[tid] += t;
            __syncthreads();
        }
        int run = srun;
        if (i < N_NODES) {
            d_off[i + 1] = run + sdata[tid];
            d_pos[i] = run + sdata[tid] - v;
        }
        __syncthreads();
        if (tid == 1023) srun = run + sdata[1023];
        __syncthreads();
    }
    if (tid == 0) d_off[0] = 0;
}

__global__ __launch_bounds__(256) void scatter_kernel(const int* __restrict__ eidx) {
    int e = blockIdx.x * 256 + threadIdx.x;
    if (e < N_EDGES) {
        int dst = eidx[N_EDGES + e];
        int p = atomicAdd(&d_pos[dst], 1);
        d_ssrc[p] = eidx[e];
        d_seid[p] = e;
    }
}

// ---------------- MMA helpers ----------------
__device__ __forceinline__ void ldsm4(uint32_t* r, const void* p) {
    unsigned a = (unsigned)__cvta_generic_to_shared(p);
    asm volatile("ldmatrix.sync.aligned.m8n8.x4.shared.b16 {%0,%1,%2,%3}, [%4];\n"
                 : "=r"(r[0]), "=r"(r[1]), "=r"(r[2]), "=r"(r[3]) : "r"(a));
}
__device__ __forceinline__ void ldsm4t(uint32_t* r, const void* p) {
    unsigned a = (unsigned)__cvta_generic_to_shared(p);
    asm volatile("ldmatrix.sync.aligned.m8n8.x4.trans.shared.b16 {%0,%1,%2,%3}, [%4];\n"
                 : "=r"(r[0]), "=r"(r[1]), "=r"(r[2]), "=r"(r[3]) : "r"(a));
}
__device__ __forceinline__ void mma_bf16(float* c, const uint32_t* a, uint32_t b0,
                                         uint32_t b1) {
    asm volatile(
        "mma.sync.aligned.m16n8k16.row.col.f32.bf16.bf16.f32 "
        "{%0,%1,%2,%3}, {%4,%5,%6,%7}, {%8,%9}, {%0,%1,%2,%3};\n"
        : "+f"(c[0]), "+f"(c[1]), "+f"(c[2]), "+f"(c[3])
        : "r"(a[0]), "r"(a[1]), "r"(a[2]), "r"(a[3]), "r"(b0), "r"(b1));
}
__device__ __forceinline__ void cp16(void* sdst, const void* gsrc, bool pred) {
    unsigned s = (unsigned)__cvta_generic_to_shared(sdst);
    int sz = pred ? 16 : 0;
    asm volatile("cp.async.cg.shared.global [%0], [%1], 16, %2;\n" ::"r"(s), "l"(gsrc),
                 "r"(sz));
}

// ---------------- unified TC GEMM (unchanged core) ----------------
__global__ __launch_bounds__(256) void gemm_tc(int asel, int wsel, int osel, int M,
                                               int N, int Kstride, int kcount) {
    const __nv_bfloat16 *Ah, *Al = nullptr, *Wh, *Wl;
    if (asel == 0) { Ah = d_xh; Al = d_xl; }
    else if (asel == 1) Ah = d_qb;
    else Ah = d_Bb;
    if (wsel == 0) { Wh = d_Wqh; Wl = d_Wql; }
    else if (wsel == 1) { Wh = d_Wgh; Wl = d_Wgl; }
    else { Wh = d_Werh; Wl = d_Werl; }
    const bool has_al = (asel == 0);

    extern __shared__ __align__(16) char dyn[];
    __nv_bfloat16* dynb = (__nv_bfloat16*)dyn;
    float* spool = (float*)(dyn + 59392);

    int tid = threadIdx.x, w = tid >> 5, l = tid & 31;
    int bm = blockIdx.y * 128, bn = blockIdx.x * 64;
    int wm = (w >> 1) * 32, wn = (w & 1) * 32;
    int kbeg = (wsel == 1) ? blockIdx.x * 512 : 0;
    if (osel == 2 && tid < 64) spool[tid] = 0.f;

    float acc[2][4][4];
#pragma unroll
    for (int a = 0; a < 2; a++)
#pragma unroll
        for (int b = 0; b < 4; b++)
#pragma unroll
            for (int c = 0; c < 4; c++) acc[a][b][c] = 0.f;

    int a_r = (l & 7) + ((l >> 3) & 1) * 8;
    int a_ko = ((l >> 4) & 1) * 8;

    auto pA = [&](int st, int p) { return dynb + (st * 2 + p) * 5120; };
    auto pW = [&](int st, int p) { return dynb + 20480 + (st * 2 + p) * 2304; };

    auto load_stage = [&](int st, int kc) {
        int nh = has_al ? 2 : 1;
        for (int p = 0; p < nh; p++) {
            const __nv_bfloat16* As = p ? Al : Ah;
            __nv_bfloat16* dst = pA(st, p);
#pragma unroll
            for (int i = 0; i < 2; i++) {
                int idx = tid + 256 * i;
                int row = idx >> 2, ch = idx & 3;
                int gr = bm + row;
                cp16(dst + row * 40 + ch * 8, As + (size_t)gr * Kstride + kc + ch * 8,
                     gr < M);
            }
        }
        for (int p = 0; p < 2; p++) {
            const __nv_bfloat16* Ws = p ? Wl : Wh;
            __nv_bfloat16* dst = pW(st, p);
            int k = tid >> 3, ch = tid & 7;
            cp16(dst + k * 72 + ch * 8, Ws + (size_t)(kc + k) * N + bn + ch * 8, true);
        }
        asm volatile("cp.async.commit_group;\n" ::);
    };

    auto compute = [&](int st) {
#pragma unroll
        for (int k16 = 0; k16 < 2; k16++) {
            uint32_t Af[2][4], Alf[2][4], Bhf[2][4], Blf[2][4];
            __nv_bfloat16* ah = pA(st, 0);
#pragma unroll
            for (int mt = 0; mt < 2; mt++)
                ldsm4(Af[mt], ah + (wm + mt * 16 + a_r) * 40 + k16 * 16 + a_ko);
            __nv_bfloat16* wh = pW(st, 0);
            __nv_bfloat16* wl = pW(st, 1);
#pragma unroll
            for (int p = 0; p < 2; p++) {
                ldsm4t(Bhf[p], wh + (k16 * 16 + a_r) * 72 + wn + p * 16 + a_ko);
                ldsm4t(Blf[p], wl + (k16 * 16 + a_r) * 72 + wn + p * 16 + a_ko);
            }
            if (has_al) {
                __nv_bfloat16* al = pA(st, 1);
#pragma unroll
                for (int mt = 0; mt < 2; mt++)
                    ldsm4(Alf[mt], al + (wm + mt * 16 + a_r) * 40 + k16 * 16 + a_ko);
            }
#pragma unroll
            for (int nt = 0; nt < 4; nt++) {
                uint32_t bh0 = Bhf[nt >> 1][(nt & 1) * 2], bh1 = Bhf[nt >> 1][(nt & 1) * 2 + 1];
                uint32_t bl0 = Blf[nt >> 1][(nt & 1) * 2], bl1 = Blf[nt >> 1][(nt & 1) * 2 + 1];
#pragma unroll
                for (int mt = 0; mt < 2; mt++) {
                    mma_bf16(acc[mt][nt], Af[mt], bh0, bh1);
                    mma_bf16(acc[mt][nt], Af[mt], bl0, bl1);
                    if (has_al) mma_bf16(acc[mt][nt], Alf[mt], bh0, bh1);
                }
            }
        }
    };

    int nIter = kcount >> 5;
    load_stage(0, kbeg);
    for (int it = 0; it < nIter; it++) {
        if (it + 1 < nIter) {
            load_stage((it + 1) & 1, kbeg + (it + 1) * 32);
            asm volatile("cp.async.wait_group 1;\n" ::);
        } else {
            asm volatile("cp.async.wait_group 0;\n" ::);
        }
        __syncthreads();
        compute(it & 1);
        __syncthreads();
    }

    int r0 = l >> 2, cq = (l & 3) * 2;
    if (osel == 0) {
        __nv_bfloat16* dstb = nullptr;
        float* dstf = nullptr;
        int coff;
        if (bn < 1024) { dstb = d_qb; coff = bn; }
        else if (bn < 2048) { dstb = d_kb; coff = bn - 1024; }
        else if (bn < 3072) { dstb = d_vb; coff = bn - 2048; }
        else { dstf = d_skip; coff = bn - 3072; }
#pragma unroll
        for (int mt = 0; mt < 2; mt++)
#pragma unroll
            for (int nt = 0; nt < 4; nt++) {
                int gcol = bn + wn + nt * 8 + cq;
                int col = coff + wn + nt * 8 + cq;
                float bb0 = d_biasc[gcol], bb1 = d_biasc[gcol + 1];
#pragma unroll
                for (int rr = 0; rr < 2; rr++) {
                    int row = bm + wm + mt * 16 + r0 + rr * 8;
                    if (row < M) {
                        float v0 = acc[mt][nt][rr * 2] + bb0;
                        float v1 = acc[mt][nt][rr * 2 + 1] + bb1;
                        if (dstf) {
                            dstf[row * 128 + col] = v0;
                            dstf[row * 128 + col + 1] = v1;
                        } else {
                            *(__nv_bfloat162*)&dstb[(size_t)row * HC + col] =
                                __floats2bfloat162_rn(v0, v1);
                        }
                    }
                }
            }
    } else if (osel == 1) {
#pragma unroll
        for (int mt = 0; mt < 2; mt++)
#pragma unroll
            for (int nt = 0; nt < 4; nt++) {
                int col = bn + wn + nt * 8 + cq;
#pragma unroll
                for (int rr = 0; rr < 2; rr++) {
                    int row = bm + wm + mt * 16 + r0 + rr * 8;
                    if (row < M) {
                        d_g[row * 128 + col] = acc[mt][nt][rr * 2];
                        d_g[row * 128 + col + 1] = acc[mt][nt][rr * 2 + 1];
                    }
                }
            }
    } else {
#pragma unroll
        for (int nt = 0; nt < 4; nt++) {
            int col = bn + wn + nt * 8 + cq;
            float s0 = 0.f, s1 = 0.f;
#pragma unroll
            for (int mt = 0; mt < 2; mt++)
#pragma unroll
                for (int rr = 0; rr < 2; rr++) {
                    int row = bm + wm + mt * 16 + r0 + rr * 8;
                    if (row < M) {
                        s0 += fmaxf(acc[mt][nt][rr * 2] + d_vout[row * 128 + col] +
                                        d_skip[row * 128 + col], 0.f);
                        s1 += fmaxf(acc[mt][nt][rr * 2 + 1] + d_vout[row * 128 + col + 1] +
                                        d_skip[row * 128 + col + 1], 0.f);
                    }
                }
#pragma unroll
            for (int off = 16; off >= 4; off >>= 1) {
                s0 += __shfl_xor_sync(0xffffffffu, s0, off);
                s1 += __shfl_xor_sync(0xffffffffu, s1, off);
            }
            if (l < 4) {
                atomicAdd(&spool[wn + nt * 8 + cq], s0);
                atomicAdd(&spool[wn + nt * 8 + cq + 1], s1);
            }
        }
        __syncthreads();
        if (tid < 64) atomicAdd(&d_pooled[bn + tid], spool[tid]);
    }
}

// ---------------- helpers for edge kernels ----------------
__device__ __forceinline__ float dot8(uint4 a, uint4 b) {
    float2 a0 = __bfloat1622float2(*(__nv_bfloat162*)&a.x);
    float2 a1 = __bfloat1622float2(*(__nv_bfloat162*)&a.y);
    float2 a2 = __bfloat1622float2(*(__nv_bfloat162*)&a.z);
    float2 a3 = __bfloat1622float2(*(__nv_bfloat162*)&a.w);
    float2 b0 = __bfloat1622float2(*(__nv_bfloat162*)&b.x);
    float2 b1 = __bfloat1622float2(*(__nv_bfloat162*)&b.y);
    float2 b2 = __bfloat1622float2(*(__nv_bfloat162*)&b.z);
    float2 b3 = __bfloat1622float2(*(__nv_bfloat162*)&b.w);
    return a0.x * b0.x + a0.y * b0.y + a1.x * b1.x + a1.y * b1.y + a2.x * b2.x +
           a2.y * b2.y + a3.x * b3.x + a3.y * b3.y;
}

// ---------------- alpha: warp per dst node over its sorted edge group ----------------
// layout: lane l, chunk j covers bf16 channels j*256 + l*8 .. +8 (head 2j + (l>>4))
__global__ __launch_bounds__(256) void edge_alpha_s(const float* __restrict__ ea) {
    int n = blockIdx.x * 8 + (threadIdx.x >> 5);
    if (n >= N_NODES) return;
    int l = threadIdx.x & 31;
    uint4 qr[4];
#pragma unroll
    for (int j = 0; j < 4; j++)
        qr[j] = *(const uint4*)&d_qb[(size_t)n * HC + j * 256 + l * 8];
    float4 gl = *(const float4*)&d_g[n * 128 + l * 4];
    int fb = (l & 3) * 4;
    int half16 = (l & 1) * 16;   // used by lanes 0..7 for kd gather
    int beg = d_off[n], end = d_off[n + 1];
    float s_acc = 0.f;
    for (int p = beg; p < end; p++) {
        int src = d_ssrc[p];
        int e = d_seid[p];
        float pd0, pd1, pd2, pd3;
        {
            const __nv_bfloat16* kp = &d_kb[(size_t)src * HC + l * 8];
            pd0 = dot8(qr[0], *(const uint4*)(kp));
            pd1 = dot8(qr[1], *(const uint4*)(kp + 256));
            pd2 = dot8(qr[2], *(const uint4*)(kp + 512));
            pd3 = dot8(qr[3], *(const uint4*)(kp + 768));
        }
#pragma unroll
        for (int off = 1; off <= 8; off <<= 1) {
            pd0 += __shfl_xor_sync(0xffffffffu, pd0, off);
            pd1 += __shfl_xor_sync(0xffffffffu, pd1, off);
            pd2 += __shfl_xor_sync(0xffffffffu, pd2, off);
            pd3 += __shfl_xor_sync(0xffffffffu, pd3, off);
        }
        // edge term: partial for head l>>2 over f in [fb, fb+4)
        float4 e4 = *(const float4*)&ea[e * F_EDGE + fb];
        float et = gl.x * e4.x + gl.y * e4.y + gl.z * e4.z + gl.w * e4.w;
        et += __shfl_xor_sync(0xffffffffu, et, 1);
        et += __shfl_xor_sync(0xffffffffu, et, 2);
        // assemble per-head alpha on lanes 0..7 (head = l)
        float kd0 = __shfl_sync(0xffffffffu, pd0, half16);  // head (l&1)
        float kd1 = __shfl_sync(0xffffffffu, pd1, half16);  // head 2+(l&1)
        float kd2 = __shfl_sync(0xffffffffu, pd2, half16);  // head 4+(l&1)
        float kd3 = __shfl_sync(0xffffffffu, pd3, half16);  // head 6+(l&1)
        float etl = __shfl_sync(0xffffffffu, et, (l & 7) * 4);
        if (l < 8) {
            int jj = l >> 1;
            float kd = (jj == 0) ? kd0 : (jj == 1) ? kd1 : (jj == 2) ? kd2 : kd3;
            float aex = __expf((kd + etl) * 0.08838834764831845f);
            d_aexp[(size_t)p * 8 + l] = aex;
            s_acc += aex;
        }
    }
    if (l < 8) d_s[n * 8 + l] = s_acc;
}

// ---------------- msg: warp per dst node; register accumulation, plain stores ----
__global__ __launch_bounds__(256) void edge_msg_s(const float* __restrict__ ea) {
    int n = blockIdx.x * 8 + (threadIdx.x >> 5);
    if (n >= N_NODES) return;
    int l = threadIdx.x & 31;
    float inv = 0.f;
    if (l < 8) {
        float s = d_s[n * 8 + l];
        inv = 0.125f / (s + 1e-16f);
    }
    int h0 = l >> 4;          // head parity for v chunks
    int fb = (l & 3) * 4;     // ea float4 base
    int hB = l >> 2;          // head for B accumulation
    int beg = d_off[n], end = d_off[n + 1];
    float acc[8];
#pragma unroll
    for (int i = 0; i < 8; i++) acc[i] = 0.f;
    float4 accB = make_float4(0.f, 0.f, 0.f, 0.f);
    for (int p = beg; p < end; p++) {
        int src = d_ssrc[p];
        int e = d_seid[p];
        float an_l = (l < 8) ? d_aexp[(size_t)p * 8 + l] * inv : 0.f;
        float an0 = __shfl_sync(0xffffffffu, an_l, h0);
        float an1 = __shfl_sync(0xffffffffu, an_l, h0 + 2);
        float an2 = __shfl_sync(0xffffffffu, an_l, h0 + 4);
        float an3 = __shfl_sync(0xffffffffu, an_l, h0 + 6);
        const __nv_bfloat16* vp = &d_vb[(size_t)src * HC + l * 8];
        uint4 v0 = *(const uint4*)(vp);
        uint4 v1 = *(const uint4*)(vp + 256);
        uint4 v2 = *(const uint4*)(vp + 512);
        uint4 v3 = *(const uint4*)(vp + 768);
        auto addv = [&](uint4 vv, float anh) {
            float2 c0 = __bfloat1622float2(*(__nv_bfloat162*)&vv.x);
            float2 c1 = __bfloat1622float2(*(__nv_bfloat162*)&vv.y);
            float2 c2 = __bfloat1622float2(*(__nv_bfloat162*)&vv.z);
            float2 c3 = __bfloat1622float2(*(__nv_bfloat162*)&vv.w);
            acc[0] += anh * c0.x;
            acc[1] += anh * c0.y;
            acc[2] += anh * c1.x;
            acc[3] += anh * c1.y;
            acc[4] += anh * c2.x;
            acc[5] += anh * c2.y;
            acc[6] += anh * c3.x;
            acc[7] += anh * c3.y;
        };
        addv(v0, an0);
        addv(v1, an1);
        addv(v2, an2);
        addv(v3, an3);
        float4 e4 = *(const float4*)&ea[e * F_EDGE + fb];
        float anB = __shfl_sync(0xffffffffu, an_l, hB);
        accB.x += anB * e4.x;
        accB.y += anB * e4.y;
        accB.z += anB * e4.z;
        accB.w += anB * e4.w;
    }
    // vout: lanes l and l+16 hold same channels (l&15)*8..+8 -> reduce, store
#pragma unroll
    for (int i = 0; i < 8; i++) acc[i] += __shfl_xor_sync(0xffffffffu, acc[i], 16);
    if (l < 16) {
        float* op = &d_vout[n * 128 + l * 8];
        *(float4*)op = make_float4(acc[0], acc[1], acc[2], acc[3]);
        *(float4*)(op + 4) = make_float4(acc[4], acc[5], acc[6], acc[7]);
    }
    // B coefficients straight to bf16 (indices l*4..+4)
    __nv_bfloat162 b01 = __floats2bfloat162_rn(accB.x, accB.y);
    __nv_bfloat162 b23 = __floats2bfloat162_rn(accB.z, accB.w);
    uint2 packed = make_uint2(*(uint32_t*)&b01, *(uint32_t*)&b23);
    *(uint2*)&d_Bb[n * 128 + l * 4] = packed;
}

// ---------------- final dot ----------------
__global__ __launch_bounds__(128) void final_dot(const float* __restrict__ Wd,
                                                 const float* __restrict__ bd,
                                                 float* __restrict__ out) {
    int t = threadIdx.x;
    float v = d_pooled[t] * Wd[t];
#pragma unroll
    for (int o = 16; o; o >>= 1) v += __shfl_xor_sync(0xffffffffu, v, o);
    __shared__ float red[4];
    if ((t & 31) == 0) red[t >> 5] = v;
    __syncthreads();
    if (t == 0) out[0] = red[0] + red[1] + red[2] + red[3] + bd[0];
}

extern "C" void kernel_launch(void* const* d_in, const int* in_sizes, int n_in,
                              void* d_out, int out_size) {
    const float* x          = (const float*)d_in[0];
    const float* edge_attr  = (const float*)d_in[1];
    const int*   edge_index = (const int*)d_in[2];
    const float* Wq = (const float*)d_in[3];
    const float* bq = (const float*)d_in[4];
    const float* Wk = (const float*)d_in[5];
    const float* bk = (const float*)d_in[6];
    const float* Wv = (const float*)d_in[7];
    const float* bv = (const float*)d_in[8];
    const float* We = (const float*)d_in[9];
    const float* Wskip = (const float*)d_in[10];
    const float* bskip = (const float*)d_in[11];
    const float* Wd = (const float*)d_in[12];
    const float* bd = (const float*)d_in[13];
    float* out = (float*)d_out;

    static void *p_pooled = nullptr, *p_cnt = nullptr;
    if (!p_pooled) {
        cudaFuncSetAttribute(gemm_tc, cudaFuncAttributeMaxDynamicSharedMemorySize, 60416);
        cudaGetSymbolAddress(&p_pooled, d_pooled);
        cudaGetSymbolAddress(&p_cnt, d_cnt);
    }

    cudaMemsetAsync(p_pooled, 0, 128 * sizeof(float), 0);
    cudaMemsetAsync(p_cnt, 0, N_NODES * sizeof(int), 0);

    // sort edges by dst (overlaps conceptually with prep/GEMM stream order)
    hist_kernel<<<(N_EDGES + 255) / 256, 256>>>(edge_index);
    scan_kernel<<<1, 1024>>>();
    scatter_kernel<<<(N_EDGES + 255) / 256, 256>>>(edge_index);

    prep_all<<<(PREP_TOTAL + 255) / 256, 256>>>(x, Wq, Wk, Wv, Wskip, bq, bk, bv, bskip,
                                                We);

    // fused q|k|v|skip : [10000,128] @ [128,3200]
    gemm_tc<<<dim3(50, 79), 256, 59648>>>(0, 0, 0, N_NODES, NQKVS, 128, 128);
    // g = q @ Wg (block-diag: each n-block uses its 512-wide k-slice)
    gemm_tc<<<dim3(2, 79), 256, 59648>>>(1, 1, 1, N_NODES, 128, 1024, 512);

    edge_alpha_s<<<1250, 256>>>(edge_attr);
    edge_msg_s<<<1250, 256>>>(edge_attr);

    // eterm = B @ Wer, fused relu(eterm+vout+skip) column-sum into pooled
    gemm_tc<<<dim3(2, 79), 256, 59648>>>(2, 2, 2, N_NODES, 128, 128, 128);

    final_dot<<<1, 128>>>(Wd, bd, out);
}